// round 15
// baseline (speedup 1.0000x reference)
#include <cuda_runtime.h>
#include <cstdint>

// ARIMA(2,1,2) eps recursion, B=1024, L=65536.
// eps_t = y[t+3] - (1+phi0)*y[t+2] - phi1*y[t+1] - mu - th0*eps_{t-1} - th1*eps_{t-2}
// Chunk-parallel (18 chunks/row, 96-step warm-up, IIR state decays ~rho^96).
// TT=96 -> 384B contiguous DRAM granule, enabling a 4-STAGE cp.async ring
// (204.8KB) with wait_group 2: TWO windows always in flight per SM to deepen
// DRAM read queue occupancy (vs 1 window in the 100.9us 3-stage baseline).
// Padded 400B smem rows (no swizzle). Warp-specialized: 128 compute + 256 IO.
// Named barriers 1 ("window ready") / 2 ("eps ready"). Store and refill use
// IDENTICAL per-warp segment ownership (same-warp program order removes the
// cross-warp store-vs-refill race).

#define L_LEN   65536
#define N_OUT   65535
#define N_EPS   65533
#define BTH     384
#define NCMP    128          // compute threads == segments per block
#define NSEG    128
#define CPR     18           // chunks per row (18*3648 >= 65533)
#define CSZ     3648         // outputs per chunk (38 tiles)
#define WUP     96           // warm-up steps (1 tile)
#define TT      96           // steps per tile
#define NTILES  39           // (WUP+CSZ)/TT
#define NSTG    4            // ring stages
#define ROWW    100          // words per segment row (96 data + 4 pad), 400B
#define STAGE_W (NSEG*ROWW)  // 12800 words per stage
#define STAGE_B (STAGE_W*4)  // 51200 bytes per stage
#define GRID    144          // 1024*18/128 == one wave

__device__ __forceinline__ uint32_t smem_u32(const void* p) {
    uint32_t a;
    asm("{ .reg .u64 t; cvta.to.shared.u64 t, %1; cvt.u32.u64 %0, t; }"
        : "=r"(a) : "l"(p));
    return a;
}

__global__ __launch_bounds__(BTH, 1)
void arima_eps_kernel(const float* __restrict__ y,
                      const float* __restrict__ phi,
                      const float* __restrict__ theta,
                      const float* __restrict__ mu,
                      float* __restrict__ out)
{
    extern __shared__ float smem[];              // 4 stages + tables
    int4* sm_p = (int4*)(smem + NSTG * STAGE_W);            // issue table
    int2* sm_q = (int2*)(smem + NSTG * STAGE_W + NSEG * 4); // store table

    const int tid = threadIdx.x;

    const float phi0 = phi[0];
    const float phi1 = phi[1];
    const float th0  = theta[0];
    const float th1  = theta[1];
    const float muv  = mu[0];
    const float c2   = 1.0f + phi0;

    // Tables. sm_p: .x = ybase+startT, .y = startT, .w = ybase (safe addr).
    //         sm_q: .x = outbase+startT, .y = startT.
    if (tid < NSEG) {
        int cid = blockIdx.x * NSEG + tid;
        int row = cid / CPR;
        int cno = cid - row * CPR;
        int4 p;
        p.y = cno * CSZ - WUP;
        p.x = row * L_LEN + p.y;
        p.z = 0;
        p.w = row * L_LEN;
        sm_p[tid] = p;
        int2 q;
        q.x = row * N_OUT + p.y;
        q.y = p.y;
        sm_q[tid] = q;
    }
    __syncthreads();

    if (tid < NCMP) {
        // ================= COMPUTE role (warps 0-3) =================
        const int s = tid;
        const int myStart = sm_p[s].y;
        float e1 = 0.f, e2 = 0.f, yc1 = 0.f, yc2 = 0.f;

        for (int k = 0; k < NTILES; ++k) {
            asm volatile("bar.sync 1, %0;" :: "n"(BTH) : "memory");

            float4* raA = (float4*)(smem + (size_t)(k % NSTG) * STAGE_W)
                        + s * (ROWW / 4);
            const float4* raB = (const float4*)(smem
                        + (size_t)((k + 1) % NSTG) * STAGE_W) + s * (ROWW / 4);

            if (myStart + k * TT == 0) { e1 = 0.f; e2 = 0.f; }

            #pragma unroll
            for (int b = 0; b < 6; ++b) {
                // v[0..15] = y[16b .. 16b+15] local, v[16..18] = peek
                float v[19];
                #pragma unroll
                for (int c = 0; c < 4; ++c) {
                    float4 q = raA[4 * b + c];
                    v[c*4+0] = q.x; v[c*4+1] = q.y;
                    v[c*4+2] = q.z; v[c*4+3] = q.w;
                }
                {
                    float4 pk = (b < 5) ? raA[4 * b + 4] : raB[0];
                    v[16] = pk.x; v[17] = pk.y; v[18] = pk.z;
                }

                #pragma unroll
                for (int e = 0; e < 16; ++e) {
                    float ynew = v[e + 3];                  // y[t+3]
                    float A = fmaf(-c2, yc2, ynew);
                    A = fmaf(-phi1, yc1, A) - muv;          // off-chain
                    float P  = fmaf(-th1, e2, A);           // 2-step-old eps
                    float ep = fmaf(-th0, e1, P);           // 1-FMA chain
                    e2 = e1; e1 = ep;
                    yc1 = yc2; yc2 = ynew;
                    v[e] = ep;                              // slot consumed
                }

                #pragma unroll
                for (int c = 0; c < 4; ++c)
                    raA[4 * b + c] =
                        make_float4(v[c*4+0], v[c*4+1], v[c*4+2], v[c*4+3]);
            }
            asm volatile("bar.arrive 2, %0;" :: "n"(BTH) : "memory");
        }
    } else {
        // ================= IO role (warps 4-11) =================
        const int it_  = tid - NCMP;             // 0..255
        const int wio  = it_ >> 5;               // IO warp 0..7
        const int lane = it_ & 31;
        const uint32_t smem0 = smem_u32(smem);

        // Unified ownership: warp wio owns segments wio*16 .. +15 for BOTH
        // store and refill (same-warp order => no store/refill race).
        // Refill: lanes 0-23 each own one 16B chunk -> one warp op = one
        // contiguous 384B gmem read into one segment row.
        const int sbase = wio * 16;
        const bool lok  = (lane < 24);
        const int cK    = lane * 4;              // element offset of chunk

        auto issue_window = [&](int m, int stage, bool headonly) {
            uint32_t sb = smem0 + (uint32_t)stage * STAGE_B;
            #pragma unroll
            for (int j = 0; j < 16; ++j) {
                int s = sbase + j;
                int4 p = sm_p[s];
                int K = m * TT + cK;
                int pos = p.y + K;
                bool ok = (unsigned)pos <= (unsigned)(L_LEN - 4);
                int so = ok ? (p.x + K) : p.w;
                int n  = ok ? 16 : 0;
                bool act = headonly ? (lane == 0) : lok;
                if (act) {
                    const float* src = y + so;
                    uint32_t dst = sb + (uint32_t)(s * (ROWW * 4) + lane * 16);
                    asm volatile("cp.async.cg.shared.global [%0], [%1], 16, %2;\n"
                                 :: "r"(dst), "l"(src), "r"(n));
                }
            }
            asm volatile("cp.async.commit_group;\n" ::: "memory");
        };

        issue_window(0, 0, false);
        issue_window(1, 1, false);
        issue_window(2, 2, false);
        issue_window(3, 3, false);
        asm volatile("cp.async.wait_group 2;\n" ::: "memory"); // w0,w1 done
        asm volatile("bar.arrive 1, %0;" :: "n"(BTH) : "memory");

        for (int k = 0; k < NTILES; ++k) {
            asm volatile("bar.sync 2, %0;" :: "n"(BTH) : "memory");

            // ---- store eps_k: 3 consecutive 128B ops per owned segment ----
            if (k >= 1) {                          // tile 0 is pure warm-up
                const float* sf = smem + (size_t)(k % NSTG) * STAGE_W;
                const int koff = k * TT;
                #pragma unroll 4
                for (int ss = 0; ss < 16; ++ss) {
                    int s = sbase + ss;
                    int2 q = sm_q[s];
                    const float* row = sf + s * ROWW;
                    int ob = q.x + koff;           // out addr for local t=0
                    int tb = q.y + koff;           // global t for local t=0
                    #pragma unroll
                    for (int h = 0; h < 3; ++h) {
                        float val = row[h * 32 + lane];
                        int tbh = tb + h * 32;
                        if (tbh + 31 < N_EPS) {
                            out[ob + h * 32 + lane] = val;
                        } else {
                            int t = tbh + lane;
                            if (t < N_OUT)
                                out[ob + h * 32 + lane] =
                                    (t < N_EPS) ? val : 0.0f;
                        }
                    }
                }
            }

            // ---- refill stage k%4 with window k+4 (windows 0..39 used;
            //      window 39 head-only: just the 16B peek per segment) ----
            if (k + NSTG <= NTILES) {
                issue_window(k + NSTG, k % NSTG, (k + NSTG) == NTILES);
            } else {
                asm volatile("cp.async.commit_group;\n" ::: "memory");
            }
            // ensure window k+2 fully resident; k+3, k+4 may stay pending
            asm volatile("cp.async.wait_group 2;\n" ::: "memory");
            if (k < NTILES - 1)
                asm volatile("bar.arrive 1, %0;" :: "n"(BTH) : "memory");
        }
    }
}

extern "C" void kernel_launch(void* const* d_in, const int* in_sizes, int n_in,
                              void* d_out, int out_size) {
    const float* y     = (const float*)d_in[0];
    const float* phi   = (const float*)d_in[1];
    const float* theta = (const float*)d_in[2];
    const float* mu    = (const float*)d_in[3];
    float* out = (float*)d_out;

    size_t smem_bytes = (size_t)NSTG * STAGE_B
                      + NSEG * sizeof(int4) + NSEG * sizeof(int2);
    cudaFuncSetAttribute(arima_eps_kernel,
                         cudaFuncAttributeMaxDynamicSharedMemorySize,
                         (int)smem_bytes);
    arima_eps_kernel<<<GRID, BTH, smem_bytes>>>(y, phi, theta, mu, out);
}

// round 16
// speedup vs baseline: 1.0235x; 1.0235x over previous
#include <cuda_runtime.h>
#include <cstdint>

// ARIMA(2,1,2) eps recursion, B=1024, L=65536.  [FINAL — R11 configuration]
// eps_t = y[t+3] - (1+phi0)*y[t+2] - phi1*y[t+1] - mu - th0*eps_{t-1} - th1*eps_{t-2}
// Chunk-parallel (18 chunks/row, 128-step warm-up, IIR state decays ~rho^128).
// Measured-optimal design:
//   * TT=128 -> 512B contiguous DRAM granule (granule curve: 128B->54%,
//     256B->61%, 512B->62%, 1024B->59% of spec BW)
//   * 3-stage cp.async ring, ONE window in flight (deeper queues measured flat)
//   * separated 64KB store / 64KB refill bursts (interleaving measured -7pts)
//   * padded 528B smem rows, all affine addressing, no swizzle
//   * warp-specialized: 128 compute threads + 256 IO threads, named barriers
//     1 ("window ready") / 2 ("eps ready"); grid=144 = one wave

#define L_LEN   65536
#define N_OUT   65535
#define N_EPS   65533
#define BTH     384
#define NCMP    128          // compute threads == segments per block
#define NSEG    128
#define CPR     18           // chunks per row (18*3712 >= 65533)
#define CSZ     3712         // outputs per chunk (29 tiles)
#define WUP     128          // warm-up steps (1 tile)
#define TT      128          // steps per tile
#define NTILES  30           // (WUP+CSZ)/TT
#define NSTG    3            // ring stages
#define ROWW    132          // words per segment row (128 data + 4 pad), 528B
#define STAGE_W (NSEG*ROWW)  // 16896 words per stage
#define STAGE_B (STAGE_W*4)  // 67584 bytes per stage
#define GRID    144          // 1024*18/128 == one wave

__device__ __forceinline__ uint32_t smem_u32(const void* p) {
    uint32_t a;
    asm("{ .reg .u64 t; cvta.to.shared.u64 t, %1; cvt.u32.u64 %0, t; }"
        : "=r"(a) : "l"(p));
    return a;
}

__global__ __launch_bounds__(BTH, 1)
void arima_eps_kernel(const float* __restrict__ y,
                      const float* __restrict__ phi,
                      const float* __restrict__ theta,
                      const float* __restrict__ mu,
                      float* __restrict__ out)
{
    extern __shared__ float smem[];              // 3 stages + tables
    int4* sm_p = (int4*)(smem + NSTG * STAGE_W);            // issue table
    int2* sm_q = (int2*)(smem + NSTG * STAGE_W + NSEG * 4); // store table

    const int tid = threadIdx.x;

    const float phi0 = phi[0];
    const float phi1 = phi[1];
    const float th0  = theta[0];
    const float th1  = theta[1];
    const float muv  = mu[0];
    const float c2   = 1.0f + phi0;

    // Tables. sm_p: .x = ybase+startT, .y = startT, .w = ybase (safe addr).
    //         sm_q: .x = outbase+startT, .y = startT.
    if (tid < NSEG) {
        int cid = blockIdx.x * NSEG + tid;
        int row = cid / CPR;
        int cno = cid - row * CPR;
        int4 p;
        p.y = cno * CSZ - WUP;
        p.x = row * L_LEN + p.y;
        p.z = 0;
        p.w = row * L_LEN;
        sm_p[tid] = p;
        int2 q;
        q.x = row * N_OUT + p.y;
        q.y = p.y;
        sm_q[tid] = q;
    }
    __syncthreads();

    if (tid < NCMP) {
        // ================= COMPUTE role (warps 0-3) =================
        const int s = tid;
        const int myStart = sm_p[s].y;
        float e1 = 0.f, e2 = 0.f, yc1 = 0.f, yc2 = 0.f;

        for (int k = 0; k < NTILES; ++k) {
            asm volatile("bar.sync 1, %0;" :: "n"(BTH) : "memory");

            float4* raA = (float4*)(smem + (size_t)(k % NSTG) * STAGE_W)
                        + s * (ROWW / 4);
            const float4* raB = (const float4*)(smem
                        + (size_t)((k + 1) % NSTG) * STAGE_W) + s * (ROWW / 4);

            if (myStart + k * TT == 0) { e1 = 0.f; e2 = 0.f; }

            #pragma unroll
            for (int b = 0; b < 8; ++b) {
                // v[0..15] = y[16b .. 16b+15] local, v[16..18] = peek
                float v[19];
                #pragma unroll
                for (int c = 0; c < 4; ++c) {
                    float4 q = raA[4 * b + c];
                    v[c*4+0] = q.x; v[c*4+1] = q.y;
                    v[c*4+2] = q.z; v[c*4+3] = q.w;
                }
                {
                    float4 pk = (b < 7) ? raA[4 * b + 4] : raB[0];
                    v[16] = pk.x; v[17] = pk.y; v[18] = pk.z;
                }

                #pragma unroll
                for (int e = 0; e < 16; ++e) {
                    float ynew = v[e + 3];                  // y[t+3]
                    float A = fmaf(-c2, yc2, ynew);
                    A = fmaf(-phi1, yc1, A) - muv;          // off-chain
                    float P  = fmaf(-th1, e2, A);           // 2-step-old eps
                    float ep = fmaf(-th0, e1, P);           // 1-FMA chain
                    e2 = e1; e1 = ep;
                    yc1 = yc2; yc2 = ynew;
                    v[e] = ep;                              // slot consumed
                }

                #pragma unroll
                for (int c = 0; c < 4; ++c)
                    raA[4 * b + c] =
                        make_float4(v[c*4+0], v[c*4+1], v[c*4+2], v[c*4+3]);
            }
            asm volatile("bar.arrive 2, %0;" :: "n"(BTH) : "memory");
        }
    } else {
        // ================= IO role (warps 4-11) =================
        const int it_  = tid - NCMP;             // 0..255
        const int wio  = it_ >> 5;               // IO warp 0..7
        const int lane = it_ & 31;
        const uint32_t smem0 = smem_u32(smem);

        // cp.async mapping: warp wio covers segments s = j*8 + wio, j=0..15;
        // lane owns 16B chunk `lane` -> each warp instruction is one fully
        // contiguous 512B gmem read into one segment row.
        const uint32_t dst0 = (uint32_t)(wio * (ROWW * 4) + lane * 16);
        const int cK = lane * 4;                 // element offset of chunk

        auto issue_window = [&](int m, int stage, bool headonly) {
            uint32_t dst = smem0 + (uint32_t)stage * STAGE_B + dst0;
            const int K = m * TT + cK;
            #pragma unroll
            for (int j = 0; j < 16; ++j) {
                int s = j * 8 + wio;
                int4 p = sm_p[s];
                int pos = p.y + K;
                bool ok = (unsigned)pos <= (unsigned)(L_LEN - 4);
                int so = ok ? (p.x + K) : p.w;
                int n  = ok ? 16 : 0;
                if (!headonly || lane == 0) {
                    const float* src = y + so;
                    asm volatile("cp.async.cg.shared.global [%0], [%1], 16, %2;\n"
                                 :: "r"(dst), "l"(src), "r"(n));
                }
                dst += 8 * (ROWW * 4);
            }
            asm volatile("cp.async.commit_group;\n" ::: "memory");
        };

        issue_window(0, 0, false);
        issue_window(1, 1, false);
        issue_window(2, 2, false);
        asm volatile("cp.async.wait_group 1;\n" ::: "memory"); // w0,w1 done
        asm volatile("bar.arrive 1, %0;" :: "n"(BTH) : "memory");

        for (int k = 0; k < NTILES; ++k) {
            asm volatile("bar.sync 2, %0;" :: "n"(BTH) : "memory");

            // ---- store eps_k: warp wio owns segments wio*16..+15,
            //      4 consecutive 128B ops per segment (512B contiguous) ----
            if (k >= 1) {                          // tile 0 is pure warm-up
                const float* sf = smem + (size_t)(k % NSTG) * STAGE_W;
                const int koff = k * TT;
                const int sbase = wio * 16;
                #pragma unroll 4
                for (int ss = 0; ss < 16; ++ss) {
                    int s = sbase + ss;
                    int2 q = sm_q[s];
                    const float* row = sf + s * ROWW;
                    int ob = q.x + koff;           // out addr for local t=0
                    int tb = q.y + koff;           // global t for local t=0
                    #pragma unroll
                    for (int h = 0; h < 4; ++h) {
                        float val = row[h * 32 + lane];
                        int tbh = tb + h * 32;
                        if (tbh + 31 < N_EPS) {
                            out[ob + h * 32 + lane] = val;
                        } else {
                            int t = tbh + lane;
                            if (t < N_OUT)
                                out[ob + h * 32 + lane] =
                                    (t < N_EPS) ? val : 0.0f;
                        }
                    }
                }
            }

            // ---- refill stage k%3 with window k+3 (windows 0..30 used;
            //      window 30 head-only: just the 16B peek per segment) ----
            if (k + NSTG <= NTILES) {
                issue_window(k + NSTG, k % NSTG, (k + NSTG) == NTILES);
            } else {
                asm volatile("cp.async.commit_group;\n" ::: "memory");
            }
            // ensure window k+2 fully resident (k+3 may stay pending)
            asm volatile("cp.async.wait_group 1;\n" ::: "memory");
            if (k < NTILES - 1)
                asm volatile("bar.arrive 1, %0;" :: "n"(BTH) : "memory");
        }
    }
}

extern "C" void kernel_launch(void* const* d_in, const int* in_sizes, int n_in,
                              void* d_out, int out_size) {
    const float* y     = (const float*)d_in[0];
    const float* phi   = (const float*)d_in[1];
    const float* theta = (const float*)d_in[2];
    const float* mu    = (const float*)d_in[3];
    float* out = (float*)d_out;

    size_t smem_bytes = (size_t)NSTG * STAGE_B
                      + NSEG * sizeof(int4) + NSEG * sizeof(int2);
    cudaFuncSetAttribute(arima_eps_kernel,
                         cudaFuncAttributeMaxDynamicSharedMemorySize,
                         (int)smem_bytes);
    arima_eps_kernel<<<GRID, BTH, smem_bytes>>>(y, phi, theta, mu, out);
}